// round 9
// baseline (speedup 1.0000x reference)
#include <cuda_runtime.h>
#include <cstdint>
#include <cstddef>

#define T_STEPS 2048
#define BATCH   64
#define IN_DIM  256
#define HID     512
#define BH      (BATCH * HID)

__device__ __align__(128) float g_xproj[(size_t)T_STEPS * BH]; // 256 MiB

// 16 clusters x 8 CTAs; CTA = 64 cols x 4 batches; 384 threads:
//   warps 0-7  (tid<256): R3 scan (smem w_rec slice, split-K, smem reduce)
//   warps 8-11 (tid>=256): x_proj producer (smem w_in slice, writes g_xproj)
#define CLS  8
#define BPC  4
#define JPC  64
#define NKC  16
#define KC   (HID / NKC)      // 32
#define HPAD 512

// smem layout (float offsets)
#define WS_OFF   0                      // w_rec slice [512][64]      131072 B
#define WI_OFF   32768                  // w_in packed [128][32] u64x2 65536 B
#define HS_OFF   49152                  // h [2][4][512]               16384 B
#define RED_OFF  53248                  // red [16][256]               16384 B
#define CTL_OFF  57344                  // mbars[2] + prog + cons
#define SMEM_FLOATS (CTL_OFF + 8)
#define SMEM_BYTES  (SMEM_FLOATS * 4)   // 229,408 B

#define TX_BYTES_PER_PHASE (CLS * 256 * 4)   // 8192
#define LEAD_WINDOW 16

typedef unsigned long long ull;

__device__ __forceinline__ void cluster_sync_() {
    asm volatile("barrier.cluster.arrive.aligned;" ::: "memory");
    asm volatile("barrier.cluster.wait.aligned;"   ::: "memory");
}
__device__ __forceinline__ void mbar_init_(unsigned a, unsigned cnt) {
    asm volatile("mbarrier.init.shared.b64 [%0], %1;" :: "r"(a), "r"(cnt) : "memory");
}
__device__ __forceinline__ void mbar_expect_tx_(unsigned a, unsigned bytes) {
    asm volatile("mbarrier.arrive.expect_tx.shared.b64 _, [%0], %1;"
                 :: "r"(a), "r"(bytes) : "memory");
}
__device__ __forceinline__ void mbar_wait_(unsigned a, unsigned parity) {
    unsigned done;
    asm volatile(
        "{\n\t.reg .pred p;\n\t"
        "mbarrier.try_wait.parity.acquire.cta.shared::cta.b64 p, [%1], %2;\n\t"
        "selp.b32 %0, 1, 0, p;\n\t}"
        : "=r"(done) : "r"(a), "r"(parity) : "memory");
    if (!done) {
        asm volatile(
            "{\n\t.reg .pred P1;\n\t"
            "WL_%=:\n\t"
            "mbarrier.try_wait.parity.acquire.cta.shared::cta.b64 P1, [%0], %1, 0x989680;\n\t"
            "@P1 bra.uni WD_%=;\n\t"
            "bra.uni WL_%=;\n\t"
            "WD_%=:\n\t}"
            :: "r"(a), "r"(parity) : "memory");
    }
}
__device__ __forceinline__ void st_async_f32_(unsigned raddr, float v, unsigned rmbar) {
    asm volatile(
        "st.async.shared::cluster.mbarrier::complete_tx::bytes.b32 [%0], %1, [%2];"
        :: "r"(raddr), "r"(__float_as_int(v)), "r"(rmbar) : "memory");
}
__device__ __forceinline__ ull fma2_(ull a, ull b, ull c) {
    ull d;
    asm("fma.rn.f32x2 %0, %1, %2, %3;" : "=l"(d) : "l"(a), "l"(b), "l"(c));
    return d;
}
__device__ __forceinline__ ull pack2_(float x) {
    ull d;
    asm("mov.b64 %0, {%1, %1};" : "=l"(d) : "r"(__float_as_int(x)));
    return d;
}
__device__ __forceinline__ ull packab_(float lo, float hi) {
    ull d;
    asm("mov.b64 %0, {%1, %2};" : "=l"(d)
        : "r"(__float_as_int(lo)), "r"(__float_as_int(hi)));
    return d;
}
__device__ __forceinline__ float selv_(const float4& A, const float4& B, int e) {
    switch (e) {
        case 0: return A.x; case 1: return A.y; case 2: return A.z; case 3: return A.w;
        case 4: return B.x; case 5: return B.y; case 6: return B.z; default: return B.w;
    }
}

__global__ __launch_bounds__(384, 1) __cluster_dims__(CLS, 1, 1)
void rnn_fused_kernel(const float* __restrict__ input,
                      const float* __restrict__ w_in,
                      const float* __restrict__ w_rec,
                      float* __restrict__ out, int write_last)
{
    extern __shared__ float smem[];
    float*      ws  = smem + WS_OFF;
    ulonglong2* wi4 = (ulonglong2*)(smem + WI_OFF);   // [128][32]
    float*      hs  = smem + HS_OFF;                  // [2][4][512]
    float*      red = smem + RED_OFF;                 // [16][256]
    volatile int* prog = (volatile int*)(smem + CTL_OFF + 4);
    volatile int* cons = (volatile int*)(smem + CTL_OFF + 5);

    const int tid  = threadIdx.x;
    const int rank = blockIdx.x & (CLS - 1);
    const int b0   = (blockIdx.x >> 3) * BPC;
    const int j0   = rank * JPC;

    // ---- prologue (all 384 threads) ----
    {
        const float4* wsrc = (const float4*)w_rec;
        float4* wdst = (float4*)ws;
        for (int i = tid; i < HID * (JPC / 4); i += 384) {
            int row = i >> 4, c4 = i & 15;
            wdst[row * 16 + c4] = wsrc[row * (HID / 4) + (j0 >> 2) + c4];
        }
        for (int i = tid; i < 128 * 32; i += 384) {
            int ip = i >> 5, jj = i & 31;
            float2 fa = *(const float2*)&w_in[(size_t)(2 * ip)     * HID + j0 + 2 * jj];
            float2 fb = *(const float2*)&w_in[(size_t)(2 * ip + 1) * HID + j0 + 2 * jj];
            ulonglong2 v;
            v.x = packab_(fa.x, fa.y);
            v.y = packab_(fb.x, fb.y);
            wi4[i] = v;
        }
        for (int i = tid; i < 2 * BPC * HPAD; i += 384) hs[i] = 0.0f;
        if (tid == 0) {
            unsigned mb = (unsigned)__cvta_generic_to_shared(smem + CTL_OFF);
            mbar_init_(mb, 1);
            mbar_init_(mb + 8, 1);
            *prog = 0;
            *cons = -1;
        }
    }
    __syncthreads();
    cluster_sync_();

    if (tid >= 256) {
        // ================= PRODUCER (warps 8-11) =================
        const int t2   = tid - 256;
        const int lane = t2 & 31;          // jj col-pair
        const int b    = t2 >> 5;          // batch (warp-uniform)
        const float* inrow = input + (size_t)(b0 + b) * IN_DIM;
        float* xdst = g_xproj + (size_t)(b0 + b) * HID + j0 + 2 * lane;
        const ulonglong2* wrow = wi4;      // [ip][jj]

#pragma unroll 1
        for (int t = 0; t < T_STEPS; t++) {
            // throttle: stay <= LEAD_WINDOW steps ahead of consumer
            while (t - *cons > LEAD_WINDOW) __nanosleep(200);

            // lane holds input[t][b][8*lane .. 8*lane+7]
            const float4* ip4 = (const float4*)(inrow + (size_t)t * (BATCH * IN_DIM));
            float4 A = ip4[lane * 2];
            float4 B = ip4[lane * 2 + 1];

            ull acc = 0ull;
#pragma unroll
            for (int ipair = 0; ipair < 128; ipair++) {
                int src = ipair >> 2;
                int e   = (ipair & 3) * 2;
                float s0 = __shfl_sync(0xffffffffu, selv_(A, B, e),     src);
                float s1 = __shfl_sync(0xffffffffu, selv_(A, B, e + 1), src);
                ulonglong2 wv = wrow[ipair * 32 + lane];
                acc = fma2_(pack2_(s0), wv.x, acc);
                acc = fma2_(pack2_(s1), wv.y, acc);
            }
            *(float2*)(xdst + (size_t)t * BH) = *(float2*)&acc;

            asm volatile("membar.cta;" ::: "memory");
            asm volatile("bar.sync 1, 128;" ::: "memory");
            if (t2 == 0) *prog = t + 1;
        }
    } else {
        // ================= CONSUMER (warps 0-7): R3 scan =================
        const int kc = tid >> 4;      // 0..15 k-chunk
        const int jg = tid & 15;      // 0..15 j-group (4 cols)
        const int ob = tid >> 6;      // 0..3 output batch
        const int oj = tid & 63;      // 0..63 output column

        const unsigned hs_loc = (unsigned)__cvta_generic_to_shared(hs);
        const unsigned mb_loc = (unsigned)__cvta_generic_to_shared(smem + CTL_OFF);
        unsigned peer_hs[CLS], peer_mb[CLS];
#pragma unroll
        for (int r = 0; r < CLS; r++) {
            asm("mapa.shared::cluster.u32 %0, %1, %2;" : "=r"(peer_hs[r]) : "r"(hs_loc), "r"(r));
            asm("mapa.shared::cluster.u32 %0, %1, %2;" : "=r"(peer_mb[r]) : "r"(mb_loc), "r"(r));
        }

        const float* wrow = ws + (kc * KC) * JPC + jg * 4;
        const size_t xbase = (size_t)(b0 + ob) * HID + j0 + oj;
        const unsigned st_off_base = (unsigned)((ob * HPAD + j0 + oj) * 4);

        int par0 = 0, par1 = 0;
        float hn = 0.0f;

#pragma unroll 1
        for (int t = 0; t < T_STEPS; t++) {
            const int q  = t & 1;
            const int qn = q ^ 1;

            // x ready? (producer leads; rarely spins)
            while (*prog < t + 1) __nanosleep(64);
            float xv = g_xproj[(size_t)t * BH + xbase];

            if (t > 0) {
                if (q == 0) { mbar_wait_(mb_loc,     par0); par0 ^= 1; }
                else        { mbar_wait_(mb_loc + 8, par1); par1 ^= 1; }
            }
            if (tid == 0 && t < T_STEPS - 1)
                mbar_expect_tx_(mb_loc + (unsigned)qn * 8, TX_BYTES_PER_PHASE);

            // split-K partials (f32x2)
            const float* hp = hs + q * BPC * HPAD + kc * KC;
            ull acc2[BPC][2];
#pragma unroll
            for (int b = 0; b < BPC; b++) { acc2[b][0] = 0ull; acc2[b][1] = 0ull; }

#pragma unroll
            for (int ki = 0; ki < KC; ki += 4) {
                ulonglong2 w0 = *(const ulonglong2*)(wrow + (ki + 0) * JPC);
                ulonglong2 w1 = *(const ulonglong2*)(wrow + (ki + 1) * JPC);
                ulonglong2 w2 = *(const ulonglong2*)(wrow + (ki + 2) * JPC);
                ulonglong2 w3 = *(const ulonglong2*)(wrow + (ki + 3) * JPC);
#pragma unroll
                for (int b = 0; b < BPC; b++) {
                    float4 h4 = *(const float4*)(hp + b * HPAD + ki);
                    acc2[b][0] = fma2_(pack2_(h4.x), w0.x, acc2[b][0]);
                    acc2[b][1] = fma2_(pack2_(h4.x), w0.y, acc2[b][1]);
                    acc2[b][0] = fma2_(pack2_(h4.y), w1.x, acc2[b][0]);
                    acc2[b][1] = fma2_(pack2_(h4.y), w1.y, acc2[b][1]);
                    acc2[b][0] = fma2_(pack2_(h4.z), w2.x, acc2[b][0]);
                    acc2[b][1] = fma2_(pack2_(h4.z), w2.y, acc2[b][1]);
                    acc2[b][0] = fma2_(pack2_(h4.w), w3.x, acc2[b][0]);
                    acc2[b][1] = fma2_(pack2_(h4.w), w3.y, acc2[b][1]);
                }
            }

#pragma unroll
            for (int b = 0; b < BPC; b++) {
                float2 p0 = *(float2*)&acc2[b][0];
                float2 p1 = *(float2*)&acc2[b][1];
                *(float4*)&red[kc * 256 + b * 64 + jg * 4] =
                    make_float4(p0.x, p0.y, p1.x, p1.y);
            }
            asm volatile("bar.sync 2, 256;" ::: "memory");
            if (tid == 0) *cons = t;

            float s = 0.0f;
#pragma unroll
            for (int c = 0; c < NKC; c++) s += red[c * 256 + tid];
            hn = tanhf(xv + s);

            // sends first (they gate cluster progress), then output store
            if (t < T_STEPS - 1) {
                unsigned doff = (unsigned)(qn * BPC * HPAD * 4) + st_off_base;
                unsigned moff = (unsigned)qn * 8;
#pragma unroll
                for (int i = 0; i < CLS; i++) {
                    int r = (rank + i) & (CLS - 1);
                    st_async_f32_(peer_hs[r] + doff, hn, peer_mb[r] + moff);
                }
            }
            out[(size_t)t * BH + xbase] = hn;
        }
        if (write_last)
            out[(size_t)T_STEPS * BH + xbase] = hn;
    }
    cluster_sync_();
}

// ---------------- launch ----------------------------------------------------
extern "C" void kernel_launch(void* const* d_in, const int* in_sizes, int n_in,
                              void* d_out, int out_size)
{
    const float* input = (const float*)d_in[0];   // [T,B,I]
    const float* w_in  = (const float*)d_in[1];   // [I,H]
    const float* w_rec = (const float*)d_in[2];   // [H,H]
    float* out = (float*)d_out;

    int write_last =
        ((size_t)out_size >= (size_t)T_STEPS * BH + (size_t)BH) ? 1 : 0;

    cudaFuncSetAttribute(rnn_fused_kernel,
                         cudaFuncAttributeMaxDynamicSharedMemorySize,
                         SMEM_BYTES);

    rnn_fused_kernel<<<BATCH / BPC * CLS, 384, SMEM_BYTES>>>(
        input, w_in, w_rec, out, write_last);
}

// round 10
// speedup vs baseline: 1.5742x; 1.5742x over previous
#include <cuda_runtime.h>
#include <cstdint>
#include <cstddef>

#define T_STEPS 2048
#define BATCH   64
#define IN_DIM  256
#define HID     512
#define BH      (BATCH * HID)

__device__ __align__(128) float g_xproj[(size_t)T_STEPS * BH]; // 256 MiB

// ---------------- Phase A: x_proj GEMM (f32x2-packed accumulators) ----------
#define GBM 64
#define GBN 64
#define GBK 32
#define GTM 4
#define GTN 4

typedef unsigned long long ull;

__device__ __forceinline__ ull fma2_(ull a, ull b, ull c) {
    ull d;
    asm("fma.rn.f32x2 %0, %1, %2, %3;" : "=l"(d) : "l"(a), "l"(b), "l"(c));
    return d;
}
__device__ __forceinline__ ull pack2_(float x) {
    ull d;
    asm("mov.b64 %0, {%1, %1};" : "=l"(d) : "r"(__float_as_int(x)));
    return d;
}

__global__ __launch_bounds__(256) void xproj_gemm_kernel(
    const float* __restrict__ A, const float* __restrict__ B)
{
    __shared__ float As[GBK][GBM];
    __shared__ float Bs[GBK][GBN];
    const int tid = threadIdx.x;
    const int tx = tid % 16, ty = tid / 16;
    const size_t mBase = (size_t)blockIdx.y * GBM;
    const int    nBase = blockIdx.x * GBN;

    ull acc[GTM][2];
#pragma unroll
    for (int i = 0; i < GTM; i++) { acc[i][0] = 0ull; acc[i][1] = 0ull; }

    for (int kt = 0; kt < IN_DIM; kt += GBK) {
#pragma unroll
        for (int s = 0; s < 2; s++) {
            int row = tid / 8 + s * 32;
            int k4  = (tid % 8) * 4;
            float4 v = *(const float4*)&A[(mBase + row) * IN_DIM + kt + k4];
            As[k4 + 0][row] = v.x; As[k4 + 1][row] = v.y;
            As[k4 + 2][row] = v.z; As[k4 + 3][row] = v.w;
        }
#pragma unroll
        for (int s = 0; s < 2; s++) {
            int row = tid / 16 + s * 16;
            int n4  = (tid % 16) * 4;
            *(float4*)&Bs[row][n4] =
                *(const float4*)&B[(size_t)(kt + row) * HID + nBase + n4];
        }
        __syncthreads();
#pragma unroll
        for (int k = 0; k < GBK; k++) {
            float a[GTM];
            *(float4*)a = *(const float4*)&As[k][ty * GTM];
            ulonglong2 b2 = *(const ulonglong2*)&Bs[k][tx * GTN];
#pragma unroll
            for (int i = 0; i < GTM; i++) {
                ull ap = pack2_(a[i]);
                acc[i][0] = fma2_(ap, b2.x, acc[i][0]);
                acc[i][1] = fma2_(ap, b2.y, acc[i][1]);
            }
        }
        __syncthreads();
    }
#pragma unroll
    for (int i = 0; i < GTM; i++) {
        size_t row = mBase + ty * GTM + i;
        float2 p0 = *(float2*)&acc[i][0];
        float2 p1 = *(float2*)&acc[i][1];
        *(float4*)&g_xproj[row * HID + nBase + tx * GTN] =
            make_float4(p0.x, p0.y, p1.x, p1.y);
    }
}

// ---------------- Phase B: cluster scan with bulk DSMEM broadcast -----------
// R3 structure: 16 clusters x 8 CTAs, 256 thr. hs is rank-major
// [2][CLS][BPC][64] so each CTA's 256 outputs are one contiguous 1KB block.
// Comm per step: STS own slot -> bar.sync -> tid0: fence.proxy.async +
// 7x cp.async.bulk (1KB) to peers (tx-counted on their phase mbar).
#define CLS  8
#define BPC  4
#define JPC  64
#define NKC  16
#define KC   (HID / NKC)      // 32

#define WS_OFF   0
#define WS_FLOATS (HID * JPC)                 // 32768 (128 KB)
#define HS_OFF   (WS_OFF + WS_FLOATS)
#define HS_FLOATS (2 * CLS * BPC * 64)        // 4096 (16 KB)
#define RED_OFF  (HS_OFF + HS_FLOATS)
#define RED_FLOATS (NKC * 256)                // 4096 (16 KB)
#define MB_OFF   (RED_OFF + RED_FLOATS)
#define SCAN_SMEM_BYTES ((MB_OFF + 8) * 4)

#define PHASE_FLOATS (CLS * BPC * 64)         // 2048 floats per phase
#define TX_BYTES_PER_PHASE (7 * BPC * 64 * 4) // 7168: 7 peers x 1KB

__device__ __forceinline__ void cluster_sync_() {
    asm volatile("barrier.cluster.arrive.aligned;" ::: "memory");
    asm volatile("barrier.cluster.wait.aligned;"   ::: "memory");
}
__device__ __forceinline__ void mbar_init_(unsigned a, unsigned cnt) {
    asm volatile("mbarrier.init.shared.b64 [%0], %1;" :: "r"(a), "r"(cnt) : "memory");
}
__device__ __forceinline__ void mbar_expect_tx_(unsigned a, unsigned bytes) {
    asm volatile("mbarrier.arrive.expect_tx.shared.b64 _, [%0], %1;"
                 :: "r"(a), "r"(bytes) : "memory");
}
__device__ __forceinline__ void mbar_wait_(unsigned a, unsigned parity) {
    unsigned done;
    asm volatile(
        "{\n\t.reg .pred p;\n\t"
        "mbarrier.try_wait.parity.acquire.cta.shared::cta.b64 p, [%1], %2;\n\t"
        "selp.b32 %0, 1, 0, p;\n\t}"
        : "=r"(done) : "r"(a), "r"(parity) : "memory");
    if (!done) {
        asm volatile(
            "{\n\t.reg .pred P1;\n\t"
            "WL_%=:\n\t"
            "mbarrier.try_wait.parity.acquire.cta.shared::cta.b64 P1, [%0], %1, 0x989680;\n\t"
            "@P1 bra.uni WD_%=;\n\t"
            "bra.uni WL_%=;\n\t"
            "WD_%=:\n\t}"
            :: "r"(a), "r"(parity) : "memory");
    }
}
__device__ __forceinline__ void bulk_dsmem_(unsigned dst, unsigned src,
                                            unsigned bytes, unsigned rmbar) {
    asm volatile(
        "cp.async.bulk.shared::cluster.shared::cta.mbarrier::complete_tx::bytes "
        "[%0], [%1], %2, [%3];"
        :: "r"(dst), "r"(src), "r"(bytes), "r"(rmbar) : "memory");
}

__global__ __launch_bounds__(256, 1) __cluster_dims__(CLS, 1, 1)
void rnn_scan_kernel(const float* __restrict__ w_rec,
                     float* __restrict__ out, int write_last)
{
    extern __shared__ float smem[];
    float* ws  = smem + WS_OFF;   // [HID][JPC]
    float* hs  = smem + HS_OFF;   // [2][CLS][BPC][64] rank-major
    float* red = smem + RED_OFF;  // [NKC][256]

    const int tid  = threadIdx.x;
    const int rank = blockIdx.x & (CLS - 1);
    const int b0   = (blockIdx.x >> 3) * BPC;
    const int j0   = rank * JPC;

    const int kc = tid >> 4;      // 0..15 k-chunk
    const int jg = tid & 15;      // 0..15 j-group (4 cols)
    const int ob = tid >> 6;      // 0..3 output batch
    const int oj = tid & 63;      // 0..63 output column

    // ---- prologue ----
    {
        const float4* wsrc = (const float4*)w_rec;
        float4* wdst = (float4*)ws;
        for (int i = tid; i < HID * (JPC / 4); i += 256) {
            int row = i >> 4, c4 = i & 15;
            wdst[row * 16 + c4] = wsrc[row * (HID / 4) + (j0 >> 2) + c4];
        }
        for (int i = tid; i < HS_FLOATS; i += 256) hs[i] = 0.0f;
        if (tid == 0) {
            unsigned mb = (unsigned)__cvta_generic_to_shared(smem + MB_OFF);
            mbar_init_(mb, 1);
            mbar_init_(mb + 8, 1);
        }
    }
    __syncthreads();
    cluster_sync_();

    const unsigned hs_loc = (unsigned)__cvta_generic_to_shared(hs);
    const unsigned mb_loc = (unsigned)__cvta_generic_to_shared(smem + MB_OFF);
    unsigned peer_hs[CLS], peer_mb[CLS];
#pragma unroll
    for (int r = 0; r < CLS; r++) {
        asm("mapa.shared::cluster.u32 %0, %1, %2;" : "=r"(peer_hs[r]) : "r"(hs_loc), "r"(r));
        asm("mapa.shared::cluster.u32 %0, %1, %2;" : "=r"(peer_mb[r]) : "r"(mb_loc), "r"(r));
    }

    const float* wrow = ws + (kc * KC) * JPC + jg * 4;
    const size_t xbase = (size_t)(b0 + ob) * HID + j0 + oj;
    // h chunk base for (kc, b): rank block kc>>1, col (kc&1)*32
    const int hchunk = (kc >> 1) * (BPC * 64) + (kc & 1) * 32;
    // own staging slot (floats): rank*256 + ob*64 + oj
    const unsigned stage_off = (unsigned)((rank * (BPC * 64) + ob * 64 + oj) * 4);
    const unsigned blk_off   = (unsigned)((rank * (BPC * 64)) * 4);

    int par0 = 0, par1 = 0;
    float hn = 0.0f;

#pragma unroll 1
    for (int t = 0; t < T_STEPS; t++) {
        const int q  = t & 1;
        const int qn = q ^ 1;

        float xv = __ldg(&g_xproj[(size_t)t * BH + xbase]);

        if (t > 0) {
            if (q == 0) { mbar_wait_(mb_loc,     par0); par0 ^= 1; }
            else        { mbar_wait_(mb_loc + 8, par1); par1 ^= 1; }
        }
        if (tid == 0 && t < T_STEPS - 1)
            mbar_expect_tx_(mb_loc + (unsigned)qn * 8, TX_BYTES_PER_PHASE);

        // ---- split-K partials (f32x2) ----
        const float* hp = hs + q * PHASE_FLOATS + hchunk;
        ull acc2[BPC][2];
#pragma unroll
        for (int b = 0; b < BPC; b++) { acc2[b][0] = 0ull; acc2[b][1] = 0ull; }

#pragma unroll
        for (int ki = 0; ki < KC; ki += 4) {
            ulonglong2 w0 = *(const ulonglong2*)(wrow + (ki + 0) * JPC);
            ulonglong2 w1 = *(const ulonglong2*)(wrow + (ki + 1) * JPC);
            ulonglong2 w2 = *(const ulonglong2*)(wrow + (ki + 2) * JPC);
            ulonglong2 w3 = *(const ulonglong2*)(wrow + (ki + 3) * JPC);
#pragma unroll
            for (int b = 0; b < BPC; b++) {
                float4 h4 = *(const float4*)(hp + b * 64 + ki);
                acc2[b][0] = fma2_(pack2_(h4.x), w0.x, acc2[b][0]);
                acc2[b][1] = fma2_(pack2_(h4.x), w0.y, acc2[b][1]);
                acc2[b][0] = fma2_(pack2_(h4.y), w1.x, acc2[b][0]);
                acc2[b][1] = fma2_(pack2_(h4.y), w1.y, acc2[b][1]);
                acc2[b][0] = fma2_(pack2_(h4.z), w2.x, acc2[b][0]);
                acc2[b][1] = fma2_(pack2_(h4.z), w2.y, acc2[b][1]);
                acc2[b][0] = fma2_(pack2_(h4.w), w3.x, acc2[b][0]);
                acc2[b][1] = fma2_(pack2_(h4.w), w3.y, acc2[b][1]);
            }
        }

#pragma unroll
        for (int b = 0; b < BPC; b++) {
            float2 p0 = *(float2*)&acc2[b][0];
            float2 p1 = *(float2*)&acc2[b][1];
            *(float4*)&red[kc * 256 + b * 64 + jg * 4] =
                make_float4(p0.x, p0.y, p1.x, p1.y);
        }
        __syncthreads();

        // ---- reduce, activate ----
        float s = 0.0f;
#pragma unroll
        for (int c = 0; c < NKC; c++) s += red[c * 256 + tid];
        hn = tanhf(xv + s);

        if (t < T_STEPS - 1) {
            // stage into own slot of next phase, then bulk-broadcast
            hs[qn * PHASE_FLOATS + rank * (BPC * 64) + ob * 64 + oj] = hn;
            __syncthreads();
            if (tid == 0) {
                asm volatile("fence.proxy.async.shared::cta;" ::: "memory");
                unsigned src  = hs_loc + (unsigned)(qn * PHASE_FLOATS * 4) + blk_off;
                unsigned moff = (unsigned)qn * 8;
#pragma unroll
                for (int i = 1; i < CLS; i++) {
                    int r = (rank + i) & (CLS - 1);
                    bulk_dsmem_(peer_hs[r] + (unsigned)(qn * PHASE_FLOATS * 4) + blk_off,
                                src, BPC * 64 * 4, peer_mb[r] + moff);
                }
            }
        }
        out[(size_t)t * BH + xbase] = hn;
    }
    if (write_last)
        out[(size_t)T_STEPS * BH + xbase] = hn;

    cluster_sync_();
}

// ---------------- launch ----------------------------------------------------
extern "C" void kernel_launch(void* const* d_in, const int* in_sizes, int n_in,
                              void* d_out, int out_size)
{
    const float* input = (const float*)d_in[0];
    const float* w_in  = (const float*)d_in[1];
    const float* w_rec = (const float*)d_in[2];
    float* out = (float*)d_out;

    int write_last =
        ((size_t)out_size >= (size_t)T_STEPS * BH + (size_t)BH) ? 1 : 0;

    cudaFuncSetAttribute(rnn_scan_kernel,
                         cudaFuncAttributeMaxDynamicSharedMemorySize,
                         SCAN_SMEM_BYTES);

    dim3 grid(HID / GBN, (T_STEPS * BATCH) / GBM);
    xproj_gemm_kernel<<<grid, 256>>>(input, w_in);

    rnn_scan_kernel<<<BATCH / BPC * CLS, 256, SCAN_SMEM_BYTES>>>(
        w_rec, out, write_last);
}